// round 7
// baseline (speedup 1.0000x reference)
#include <cuda_runtime.h>

#define NTOK 262144
#define NSEG 4096
#define DDIM 256
#define ADIM 128
#define NB   256      // scan blocks: NTOK / 1024

// ---------------- scratch (no allocations allowed) ----------------
__device__ int                d_seg[NTOK];
__device__ int                d_ends[NSEG];
__device__ unsigned long long d_desc[NB];     // decoupled-lookback descriptors
__device__ float              d_Mt[DDIM * DDIM];
__device__ float              d_V[NSEG * DDIM];
__device__ float              d_logits[NTOK];

// packed f32x2 helpers (Blackwell FFMA2 path)
__device__ __forceinline__ unsigned long long pack2(float lo, float hi) {
    unsigned long long r;
    asm("mov.b64 %0, {%1, %2};" : "=l"(r) : "f"(lo), "f"(hi));
    return r;
}
__device__ __forceinline__ unsigned long long fma2(unsigned long long a,
                                                   unsigned long long b,
                                                   unsigned long long c) {
    unsigned long long d;
    asm("fma.rn.f32x2 %0, %1, %2, %3;" : "=l"(d) : "l"(a), "l"(b), "l"(c));
    return d;
}
__device__ __forceinline__ void unpack2(unsigned long long v, float& lo, float& hi) {
    asm("mov.b64 {%0, %1}, %2;" : "=f"(lo), "=f"(hi) : "l"(v));
}

// ---------------- init (reset lookback flags each replay) ----------------
__global__ void initK() {
    int t = threadIdx.x;
    if (t < NB) d_desc[t] = 0ull;
}

// ---------------- single-pass scan of `queries` -> seg[] + ends[] ----------------
__global__ void scanF(const int* __restrict__ q) {
    __shared__ int warpOff[8];
    __shared__ int warpSums[8];
    __shared__ int blockAgg;
    __shared__ int blockPrefix;

    int t = threadIdx.x, b = blockIdx.x;
    int lane = t & 31, wid = t >> 5;

    int4 v = ((const int4*)q)[b * 256 + t];
    int s = v.x + v.y + v.z + v.w;

    int inc = s;
#pragma unroll
    for (int off = 1; off < 32; off <<= 1) {
        int n = __shfl_up_sync(0xffffffffu, inc, off);
        if (lane >= off) inc += n;
    }
    if (lane == 31) warpSums[wid] = inc;
    __syncthreads();

    if (wid == 0 && lane < 8) {
        int w  = warpSums[lane];
        int wi = w;
#pragma unroll
        for (int off = 1; off < 8; off <<= 1) {
            int n = __shfl_up_sync(0xffu, wi, off);
            if (lane >= off) wi += n;
        }
        warpOff[lane] = wi - w;
        if (lane == 7) {
            blockAgg = wi;
            unsigned long long pub = ((b == 0) ? (2ull << 32) : (1ull << 32))
                                     | (unsigned)wi;
            atomicExch(&d_desc[b], pub);
            if (b == 0) blockPrefix = 0;
        }
    }
    __syncthreads();

    if (b > 0 && wid == 0) {
        long long run = 0;
        int offbase = 1;
        while (true) {
            int idx = b - (offbase + lane);
            int st; unsigned val;
            if (idx >= 0) {
                unsigned long long d =
                    *((volatile const unsigned long long*)(d_desc + idx));
                st = (int)(d >> 32); val = (unsigned)d;
            } else { st = 2; val = 0; }
            unsigned ready = __ballot_sync(0xffffffffu, st != 0);
            if (ready != 0xffffffffu) continue;
            unsigned pm = __ballot_sync(0xffffffffu, st == 2);
            unsigned contrib;
            if (pm) {
                int nearest = __ffs(pm) - 1;
                contrib = (lane <= nearest) ? val : 0u;
            } else {
                contrib = val;
            }
#pragma unroll
            for (int o = 16; o > 0; o >>= 1)
                contrib += __shfl_down_sync(0xffffffffu, contrib, o);
            contrib = __shfl_sync(0xffffffffu, contrib, 0);
            run += contrib;
            if (pm) break;
            offbase += 32;
        }
        if (lane == 0) {
            blockPrefix = (int)run;
            atomicExch(&d_desc[b],
                       (2ull << 32) | (unsigned)((int)run + blockAgg));
        }
    }
    __syncthreads();

    int p  = blockPrefix + warpOff[wid] + inc - s;
    int g0 = (b * 256 + t) * 4;
    int4 sv;
    sv.x = p; if (v.x) { d_ends[p] = g0 + 0; p++; }
    sv.y = p; if (v.y) { d_ends[p] = g0 + 1; p++; }
    sv.z = p; if (v.z) { d_ends[p] = g0 + 2; p++; }
    sv.w = p; if (v.w) { d_ends[p] = g0 + 3; p++; }
    ((int4*)d_seg)[b * 256 + t] = sv;
}

// ---------------- Mt[k][n] = sum_a Wq[a][k] * Wk[a][n] ----------------
__global__ void mtK(const float* __restrict__ Wq, const float* __restrict__ Wk) {
    int k = blockIdx.x;
    int n = threadIdx.x;
    float acc = 0.0f;
#pragma unroll 8
    for (int a = 0; a < ADIM; a++)
        acc += __ldg(Wq + a * DDIM + k) * __ldg(Wk + a * DDIM + n);
    d_Mt[k * DDIM + n] = acc;
}

// ---------------- V = gather(X, ends) @ Mt ----------------
// BM=32, BN=64, BK=64; 64 threads; 4x8 micro-tile via packed f32x2 FFMA2.
// B smem uses XOR-4 deswizzle: phys_word = w ^ ((w>>3)&4), conflict-free
// 8-lane phases for both STS.128 and the 8-wide column LDS.128 reads.
__global__ void gemmV(const float* __restrict__ X) {
    __shared__ __align__(16) float As[32][68];
    __shared__ __align__(16) float Bs[64][68];
    __shared__ int endsS[32];

    int t  = threadIdx.x;        // 0..63
    int rb = blockIdx.y;         // 0..127 (32 segments each)
    int nb = blockIdx.x;         // 0..3   (64 cols each)
    if (t < 32) endsS[t] = d_ends[rb * 32 + t];
    __syncthreads();

    int tx = t & 7;              // 8 col-groups of 8 cols
    int ty = t >> 3;             // 8 row-groups of 4 rows
    int txs = tx & 4;            // XOR term for this thread's B words
    int wlo = (8 * tx) ^ txs;         // phys word of logical cols 8tx..8tx+3
    int whi = (8 * tx + 4) ^ txs;     // phys word of logical cols 8tx+4..8tx+7

    unsigned long long acc[4][4];
#pragma unroll
    for (int r = 0; r < 4; r++)
#pragma unroll
        for (int c = 0; c < 4; c++) acc[r][c] = 0ull;

    for (int kt = 0; kt < 4; kt++) {
        // A tile: 32 rows x 64 k = 512 float4, 8 per thread (gathered rows)
#pragma unroll
        for (int l = 0; l < 8; l++) {
            int f   = t + l * 64;
            int row = f >> 4;
            int k4  = f & 15;
            float4 x = __ldg((const float4*)(X + (size_t)endsS[row] * DDIM + kt * 64) + k4);
            *(float4*)&As[row][k4 * 4] = x;
        }
        // B tile: 64 k x 64 n = 1024 float4, 16 per thread, deswizzled store
#pragma unroll
        for (int l = 0; l < 16; l++) {
            int f  = t + l * 64;
            int kk = f >> 4;
            int n4 = f & 15;
            int w  = 4 * n4;
            int pw = w ^ ((w >> 3) & 4);
            float4 bv = __ldg((const float4*)(d_Mt + (size_t)(kt * 64 + kk) * DDIM + nb * 64) + n4);
            *(float4*)&Bs[kk][pw] = bv;
        }
        __syncthreads();
#pragma unroll 8
        for (int kk = 0; kk < 64; kk++) {
            unsigned long long A0 = pack2(As[ty * 4 + 0][kk], As[ty * 4 + 0][kk]);
            unsigned long long A1 = pack2(As[ty * 4 + 1][kk], As[ty * 4 + 1][kk]);
            unsigned long long A2 = pack2(As[ty * 4 + 2][kk], As[ty * 4 + 2][kk]);
            unsigned long long A3 = pack2(As[ty * 4 + 3][kk], As[ty * 4 + 3][kk]);
            ulonglong2 blo = *(const ulonglong2*)&Bs[kk][wlo];  // cols 8tx..+3
            ulonglong2 bhi = *(const ulonglong2*)&Bs[kk][whi];  // cols 8tx+4..+7
            acc[0][0] = fma2(A0, blo.x, acc[0][0]);
            acc[0][1] = fma2(A0, blo.y, acc[0][1]);
            acc[0][2] = fma2(A0, bhi.x, acc[0][2]);
            acc[0][3] = fma2(A0, bhi.y, acc[0][3]);
            acc[1][0] = fma2(A1, blo.x, acc[1][0]);
            acc[1][1] = fma2(A1, blo.y, acc[1][1]);
            acc[1][2] = fma2(A1, bhi.x, acc[1][2]);
            acc[1][3] = fma2(A1, bhi.y, acc[1][3]);
            acc[2][0] = fma2(A2, blo.x, acc[2][0]);
            acc[2][1] = fma2(A2, blo.y, acc[2][1]);
            acc[2][2] = fma2(A2, bhi.x, acc[2][2]);
            acc[2][3] = fma2(A2, bhi.y, acc[2][3]);
            acc[3][0] = fma2(A3, blo.x, acc[3][0]);
            acc[3][1] = fma2(A3, blo.y, acc[3][1]);
            acc[3][2] = fma2(A3, bhi.x, acc[3][2]);
            acc[3][3] = fma2(A3, bhi.y, acc[3][3]);
        }
        __syncthreads();
    }

#pragma unroll
    for (int r = 0; r < 4; r++) {
        float4 o0, o1;
        unpack2(acc[r][0], o0.x, o0.y); unpack2(acc[r][1], o0.z, o0.w);
        unpack2(acc[r][2], o1.x, o1.y); unpack2(acc[r][3], o1.z, o1.w);
        float* dst = d_V + (size_t)(rb * 32 + ty * 4 + r) * DDIM + nb * 64 + tx * 8;
        *(float4*)dst       = o0;
        *(float4*)(dst + 4) = o1;
    }
}

// ---------------- logits: warp per token, streaming X ----------------
__global__ void logitsK(const float* __restrict__ X) {
    int token = blockIdx.x * 16 + (threadIdx.x >> 5);
    int lane  = threadIdx.x & 31;
    int s = d_seg[token];
    const float4* xr = (const float4*)X + (size_t)token * 64;
    const float4* vr = (const float4*)d_V + (size_t)s * 64;

    float4 a = __ldcs(xr + lane);
    float4 b = __ldg(vr + lane);
    float p = a.x * b.x + a.y * b.y + a.z * b.z + a.w * b.w;
    a = __ldcs(xr + lane + 32);
    b = __ldg(vr + lane + 32);
    p += a.x * b.x + a.y * b.y + a.z * b.z + a.w * b.w;

#pragma unroll
    for (int off = 16; off > 0; off >>= 1)
        p += __shfl_down_sync(0xffffffffu, p, off);
    if (lane == 0) d_logits[token] = p;
}

// ---------------- segmented softmax: block per segment over L2-hot logits ----------------
__global__ void softmaxK(float* __restrict__ out) {
    __shared__ float red[4];
    __shared__ int sStart, sLen;
    int b = blockIdx.x, t = threadIdx.x;
    int lane = t & 31, wid = t >> 5;

    if (t == 0) {
        int e  = d_ends[b];
        int st = (b == 0) ? 0 : (d_ends[b - 1] + 1);
        sStart = st; sLen = e - st + 1;
    }
    __syncthreads();
    int start = sStart, len = sLen;

    float m = -INFINITY;
    for (int i = t; i < len; i += 128)
        m = fmaxf(m, d_logits[start + i]);
#pragma unroll
    for (int o = 16; o > 0; o >>= 1)
        m = fmaxf(m, __shfl_xor_sync(0xffffffffu, m, o));
    if (lane == 0) red[wid] = m;
    __syncthreads();
    m = fmaxf(fmaxf(red[0], red[1]), fmaxf(red[2], red[3]));

    float s = 0.0f;
    for (int i = t; i < len; i += 128)
        s += __expf(d_logits[start + i] - m);
#pragma unroll
    for (int o = 16; o > 0; o >>= 1)
        s += __shfl_xor_sync(0xffffffffu, s, o);
    __syncthreads();
    if (lane == 0) red[wid] = s;
    __syncthreads();
    float invS = 1.0f / (red[0] + red[1] + red[2] + red[3]);

    for (int i = t; i < len; i += 128)
        out[start + i] = __expf(d_logits[start + i] - m) * invS;
}

extern "C" void kernel_launch(void* const* d_in, const int* in_sizes, int n_in,
                              void* d_out, int out_size) {
    const float* X  = (const float*)d_in[0];
    const int*   q  = (const int*)d_in[1];
    const float* Wq = (const float*)d_in[3];
    const float* Wk = (const float*)d_in[4];
    float* out = (float*)d_out;

    initK<<<1, 256>>>();
    scanF<<<NB, 256>>>(q);
    mtK<<<DDIM, DDIM>>>(Wq, Wk);
    gemmV<<<dim3(4, 128), 64>>>(X);
    logitsK<<<NTOK / 16, 512>>>(X);
    softmaxK<<<NSEG, 128>>>(out);
}

// round 10
// speedup vs baseline: 1.1873x; 1.1873x over previous
#include <cuda_runtime.h>

#define NTOK 262144
#define NSEG 4096
#define DDIM 256
#define ADIM 128
#define NB   256      // scan blocks: NTOK / 1024

// ---------------- scratch (no allocations allowed) ----------------
__device__ int                d_seg[NTOK];
__device__ int                d_ends[NSEG];
__device__ unsigned long long d_desc[NB];     // decoupled-lookback descriptors
__device__ float              d_Mt[DDIM * DDIM];
__device__ float              d_V[NSEG * DDIM];
__device__ float              d_logits[NTOK];

// packed f32x2 helpers (Blackwell FFMA2 path)
__device__ __forceinline__ unsigned long long pack2(float lo, float hi) {
    unsigned long long r;
    asm("mov.b64 %0, {%1, %2};" : "=l"(r) : "f"(lo), "f"(hi));
    return r;
}
__device__ __forceinline__ unsigned long long fma2(unsigned long long a,
                                                   unsigned long long b,
                                                   unsigned long long c) {
    unsigned long long d;
    asm("fma.rn.f32x2 %0, %1, %2, %3;" : "=l"(d) : "l"(a), "l"(b), "l"(c));
    return d;
}
__device__ __forceinline__ void unpack2(unsigned long long v, float& lo, float& hi) {
    asm("mov.b64 {%0, %1}, %2;" : "=f"(lo), "=f"(hi) : "l"(v));
}

// ---------------- init (reset lookback flags each replay) ----------------
__global__ void initK() {
    int t = threadIdx.x;
    if (t < NB) d_desc[t] = 0ull;
}

// ---------------- single-pass scan of `queries` -> seg[] + ends[] ----------------
__global__ void scanF(const int* __restrict__ q) {
    __shared__ int warpOff[8];
    __shared__ int warpSums[8];
    __shared__ int blockAgg;
    __shared__ int blockPrefix;

    int t = threadIdx.x, b = blockIdx.x;
    int lane = t & 31, wid = t >> 5;

    int4 v = ((const int4*)q)[b * 256 + t];
    int s = v.x + v.y + v.z + v.w;

    int inc = s;
#pragma unroll
    for (int off = 1; off < 32; off <<= 1) {
        int n = __shfl_up_sync(0xffffffffu, inc, off);
        if (lane >= off) inc += n;
    }
    if (lane == 31) warpSums[wid] = inc;
    __syncthreads();

    if (wid == 0 && lane < 8) {
        int w  = warpSums[lane];
        int wi = w;
#pragma unroll
        for (int off = 1; off < 8; off <<= 1) {
            int n = __shfl_up_sync(0xffu, wi, off);
            if (lane >= off) wi += n;
        }
        warpOff[lane] = wi - w;
        if (lane == 7) {
            blockAgg = wi;
            unsigned long long pub = ((b == 0) ? (2ull << 32) : (1ull << 32))
                                     | (unsigned)wi;
            atomicExch(&d_desc[b], pub);
            if (b == 0) blockPrefix = 0;
        }
    }
    __syncthreads();

    if (b > 0 && wid == 0) {
        long long run = 0;
        int offbase = 1;
        while (true) {
            int idx = b - (offbase + lane);
            int st; unsigned val;
            if (idx >= 0) {
                unsigned long long d =
                    *((volatile const unsigned long long*)(d_desc + idx));
                st = (int)(d >> 32); val = (unsigned)d;
            } else { st = 2; val = 0; }
            unsigned ready = __ballot_sync(0xffffffffu, st != 0);
            if (ready != 0xffffffffu) continue;
            unsigned pm = __ballot_sync(0xffffffffu, st == 2);
            unsigned contrib;
            if (pm) {
                int nearest = __ffs(pm) - 1;
                contrib = (lane <= nearest) ? val : 0u;
            } else {
                contrib = val;
            }
#pragma unroll
            for (int o = 16; o > 0; o >>= 1)
                contrib += __shfl_down_sync(0xffffffffu, contrib, o);
            contrib = __shfl_sync(0xffffffffu, contrib, 0);
            run += contrib;
            if (pm) break;
            offbase += 32;
        }
        if (lane == 0) {
            blockPrefix = (int)run;
            atomicExch(&d_desc[b],
                       (2ull << 32) | (unsigned)((int)run + blockAgg));
        }
    }
    __syncthreads();

    int p  = blockPrefix + warpOff[wid] + inc - s;
    int g0 = (b * 256 + t) * 4;
    int4 sv;
    sv.x = p; if (v.x) { d_ends[p] = g0 + 0; p++; }
    sv.y = p; if (v.y) { d_ends[p] = g0 + 1; p++; }
    sv.z = p; if (v.z) { d_ends[p] = g0 + 2; p++; }
    sv.w = p; if (v.w) { d_ends[p] = g0 + 3; p++; }
    ((int4*)d_seg)[b * 256 + t] = sv;
}

// ---------------- Mt[k][n] = sum_a Wq[a][k] * Wk[a][n] ----------------
__global__ void mtK(const float* __restrict__ Wq, const float* __restrict__ Wk) {
    int k = blockIdx.x;
    int n = threadIdx.x;
    float acc = 0.0f;
#pragma unroll 8
    for (int a = 0; a < ADIM; a++)
        acc += __ldg(Wq + a * DDIM + k) * __ldg(Wk + a * DDIM + n);
    d_Mt[k * DDIM + n] = acc;
}

// ---------------- V = gather(X, ends) @ Mt ----------------
// BM=64, BN=64, BK=64; 256 threads; 4x4 micro-tile via FFMA2.
// Register-prefetch double buffering: next tile's LDGs issue BEFORE the
// 64-kk compute loop, hiding the ~600cyc gathered-DRAM latency.
__global__ void gemmV(const float* __restrict__ X) {
    __shared__ __align__(16) float As[64][68];
    __shared__ __align__(16) float Bs[64][68];
    __shared__ int endsS[64];

    int t  = threadIdx.x;        // 0..255
    int rb = blockIdx.y;         // 0..63 (64 segments each)
    int nb = blockIdx.x;         // 0..3  (64 cols each)
    if (t < 64) endsS[t] = d_ends[rb * 64 + t];
    __syncthreads();

    int tx = t & 15;             // cols 4tx..4tx+3
    int ty = t >> 4;             // rows 4ty..4ty+3

    // per-thread load coordinates (4 float4 per tile for each of A and B)
    int arow[4], ak4[4], bkk[4], bn4[4];
#pragma unroll
    for (int l = 0; l < 4; l++) {
        int f = t + l * 256;
        arow[l] = f >> 4;  ak4[l] = f & 15;
        bkk[l]  = f >> 4;  bn4[l] = f & 15;
    }

    float4 pa[4], pb[4];
    // prefetch tile kt=0
#pragma unroll
    for (int l = 0; l < 4; l++) {
        pa[l] = __ldg((const float4*)(X + (size_t)endsS[arow[l]] * DDIM) + ak4[l]);
        pb[l] = __ldg((const float4*)(d_Mt + (size_t)bkk[l] * DDIM + nb * 64) + bn4[l]);
    }

    unsigned long long acc[4][2];
#pragma unroll
    for (int r = 0; r < 4; r++) { acc[r][0] = 0ull; acc[r][1] = 0ull; }

    for (int kt = 0; kt < 4; kt++) {
        // store prefetched tile to smem
#pragma unroll
        for (int l = 0; l < 4; l++) {
            *(float4*)&As[arow[l]][ak4[l] * 4] = pa[l];
            *(float4*)&Bs[bkk[l]][bn4[l] * 4] = pb[l];
        }
        __syncthreads();

        // issue next tile's loads (latency hidden behind compute below)
        if (kt < 3) {
            int ko = (kt + 1) * 64;
#pragma unroll
            for (int l = 0; l < 4; l++) {
                pa[l] = __ldg((const float4*)(X + (size_t)endsS[arow[l]] * DDIM + ko) + ak4[l]);
                pb[l] = __ldg((const float4*)(d_Mt + (size_t)(ko + bkk[l]) * DDIM + nb * 64) + bn4[l]);
            }
        }

#pragma unroll 8
        for (int kk = 0; kk < 64; kk++) {
            const ulonglong2 bv = *(const ulonglong2*)&Bs[kk][tx * 4];
            float a0 = As[ty * 4 + 0][kk];
            float a1 = As[ty * 4 + 1][kk];
            float a2 = As[ty * 4 + 2][kk];
            float a3 = As[ty * 4 + 3][kk];
            unsigned long long A0 = pack2(a0, a0);
            unsigned long long A1 = pack2(a1, a1);
            unsigned long long A2 = pack2(a2, a2);
            unsigned long long A3 = pack2(a3, a3);
            acc[0][0] = fma2(A0, bv.x, acc[0][0]);
            acc[0][1] = fma2(A0, bv.y, acc[0][1]);
            acc[1][0] = fma2(A1, bv.x, acc[1][0]);
            acc[1][1] = fma2(A1, bv.y, acc[1][1]);
            acc[2][0] = fma2(A2, bv.x, acc[2][0]);
            acc[2][1] = fma2(A2, bv.y, acc[2][1]);
            acc[3][0] = fma2(A3, bv.x, acc[3][0]);
            acc[3][1] = fma2(A3, bv.y, acc[3][1]);
        }
        __syncthreads();
    }

#pragma unroll
    for (int r = 0; r < 4; r++) {
        float4 o;
        unpack2(acc[r][0], o.x, o.y);
        unpack2(acc[r][1], o.z, o.w);
        *(float4*)(d_V + (size_t)(rb * 64 + ty * 4 + r) * DDIM + nb * 64 + tx * 4) = o;
    }
}

// ---------------- logits: warp per token, streaming X ----------------
__global__ void logitsK(const float* __restrict__ X) {
    int token = blockIdx.x * 8 + (threadIdx.x >> 5);
    int lane  = threadIdx.x & 31;
    int s = d_seg[token];
    const float4* xr = (const float4*)X + (size_t)token * 64;
    const float4* vr = (const float4*)d_V + (size_t)s * 64;

    float4 a = __ldcs(xr + lane);
    float4 b = __ldg(vr + lane);
    float p = a.x * b.x + a.y * b.y + a.z * b.z + a.w * b.w;
    a = __ldcs(xr + lane + 32);
    b = __ldg(vr + lane + 32);
    p += a.x * b.x + a.y * b.y + a.z * b.z + a.w * b.w;

#pragma unroll
    for (int off = 16; off > 0; off >>= 1)
        p += __shfl_down_sync(0xffffffffu, p, off);
    if (lane == 0) d_logits[token] = p;
}

// ---------------- segmented softmax: block per segment over L2-hot logits ----------------
__global__ void softmaxK(float* __restrict__ out) {
    __shared__ float red[4];
    __shared__ int sStart, sLen;
    int b = blockIdx.x, t = threadIdx.x;
    int lane = t & 31, wid = t >> 5;

    if (t == 0) {
        int e  = d_ends[b];
        int st = (b == 0) ? 0 : (d_ends[b - 1] + 1);
        sStart = st; sLen = e - st + 1;
    }
    __syncthreads();
    int start = sStart, len = sLen;

    float m = -INFINITY;
    for (int i = t; i < len; i += 128)
        m = fmaxf(m, d_logits[start + i]);
#pragma unroll
    for (int o = 16; o > 0; o >>= 1)
        m = fmaxf(m, __shfl_xor_sync(0xffffffffu, m, o));
    if (lane == 0) red[wid] = m;
    __syncthreads();
    m = fmaxf(fmaxf(red[0], red[1]), fmaxf(red[2], red[3]));

    float s = 0.0f;
    for (int i = t; i < len; i += 128)
        s += __expf(d_logits[start + i] - m);
#pragma unroll
    for (int o = 16; o > 0; o >>= 1)
        s += __shfl_xor_sync(0xffffffffu, s, o);
    __syncthreads();
    if (lane == 0) red[wid] = s;
    __syncthreads();
    float invS = 1.0f / (red[0] + red[1] + red[2] + red[3]);

    for (int i = t; i < len; i += 128)
        out[start + i] = __expf(d_logits[start + i] - m) * invS;
}

extern "C" void kernel_launch(void* const* d_in, const int* in_sizes, int n_in,
                              void* d_out, int out_size) {
    const float* X  = (const float*)d_in[0];
    const int*   q  = (const int*)d_in[1];
    const float* Wq = (const float*)d_in[3];
    const float* Wk = (const float*)d_in[4];
    float* out = (float*)d_out;

    initK<<<1, 256>>>();
    scanF<<<NB, 256>>>(q);
    mtK<<<DDIM, DDIM>>>(Wq, Wk);
    gemmV<<<dim3(4, 64), 256>>>(X);
    logitsK<<<NTOK / 8, 256>>>(X);
    softmaxK<<<NSEG, 128>>>(out);
}